// round 11
// baseline (speedup 1.0000x reference)
#include <cuda_runtime.h>
#include <cuda_bf16.h>
#include <cstdint>

// Problem constants
#define B_SZ  512
#define ZI    16
#define T_SZ  8
#define D     128
#define MROWS (B_SZ * ZI)   // 8192 img rows
#define NROWS (B_SZ * T_SZ) // 4096 text rows

// GEMM tiling: block 128x64, warp tile 32x32, fp8 k-step 32
#define BM    128
#define BN    64
#define LDS8  144           // padded fp8 row stride in bytes (conflict-free)
#define GEMM_THREADS 256
#define NBX   (NROWS / BN)  // 64
#define NBY   (MROWS / BM)  // 64

// dynamic smem layout (bytes)
#define SMEM_A     0
#define SMEM_B     (BM * LDS8)              // 18432
#define SMEM_EBUF  (SMEM_B + BN * LDS8)     // 27648
#define SMEM_TOTAL (SMEM_EBUF + 4 * 64 * 4) // 28672

// -------- device scratch (no allocations; zero-initialized) --------
__device__ uint4 g_imgn8[MROWS * D / 16];    // normalized img, e4m3, 1 MB
__device__ uint4 g_textn8[NROWS * D / 16];   // normalized text, e4m3, 0.5 MB
__device__ float g_part_i2t[B_SZ * 128];     // [bi][bx*2+wc] partial exp-sums
__device__ float g_part_t2i[NROWS * NBY];    // [col][by] partial exp-sums (transposed)
__device__ float g_mdiag[B_SZ * T_SZ];       // M[bi,bi,t]
__device__ float g_blockpart[B_SZ / 8];      // per-block loss partials (64)

// ============================================================
// Kernel 1: L2 normalize rows of 128 f32 -> e4m3; 4 rows per warp
// ============================================================
__global__ void normalize_kernel(const float* __restrict__ img,
                                 const float* __restrict__ text) {
    int gw   = (blockIdx.x * blockDim.x + threadIdx.x) >> 5;  // warp id
    int lane = threadIdx.x & 31;
    int r0 = gw * 4;                       // rows r0..r0+3 (never straddle tensors)
    const float* src;
    uint32_t* dst;
    int lrow;
    if (r0 < MROWS) { src = img;  lrow = r0;         dst = reinterpret_cast<uint32_t*>(g_imgn8); }
    else            { src = text; lrow = r0 - MROWS; dst = reinterpret_cast<uint32_t*>(g_textn8); }
    float4 v[4];
#pragma unroll
    for (int r = 0; r < 4; r++)
        v[r] = reinterpret_cast<const float4*>(src)[(lrow + r) * 32 + lane];
    float ss[4];
#pragma unroll
    for (int r = 0; r < 4; r++)
        ss[r] = v[r].x * v[r].x + v[r].y * v[r].y + v[r].z * v[r].z + v[r].w * v[r].w;
#pragma unroll
    for (int s = 16; s > 0; s >>= 1) {
#pragma unroll
        for (int r = 0; r < 4; r++)
            ss[r] += __shfl_xor_sync(0xffffffffu, ss[r], s);
    }
#pragma unroll
    for (int r = 0; r < 4; r++) {
        float inv = rsqrtf(fmaxf(ss[r], 1e-24f));
        uint32_t pack;
        asm("{ .reg .b16 lo, hi;\n\t"
            "cvt.rn.satfinite.e4m3x2.f32 lo, %2, %1;\n\t"
            "cvt.rn.satfinite.e4m3x2.f32 hi, %4, %3;\n\t"
            "mov.b32 %0, {lo, hi}; }"
            : "=r"(pack)
            : "f"(v[r].x * inv), "f"(v[r].y * inv), "f"(v[r].z * inv), "f"(v[r].w * inv));
        dst[(lrow + r) * 32 + lane] = pack;
    }
}

// ============================================================
// Kernel 2: fp8 GEMM 128x64 block / 32x32 warp tile, 3 CTAs/SM
// ============================================================
extern __shared__ char smem_raw[];

__device__ __forceinline__ void mma_fp8(float* c, const uint32_t* a, uint32_t b0, uint32_t b1) {
    asm volatile(
        "mma.sync.aligned.m16n8k32.row.col.f32.e4m3.e4m3.f32 "
        "{%0,%1,%2,%3}, {%4,%5,%6,%7}, {%8,%9}, {%0,%1,%2,%3};\n"
        : "+f"(c[0]), "+f"(c[1]), "+f"(c[2]), "+f"(c[3])
        : "r"(a[0]), "r"(a[1]), "r"(a[2]), "r"(a[3]), "r"(b0), "r"(b1));
}

__global__ void __launch_bounds__(GEMM_THREADS, 3)
gemm_kernel() {
    char* As = smem_raw + SMEM_A;    // [128][144] fp8
    char* Bs = smem_raw + SMEM_B;    // [64][144] fp8
    float* ebuf = reinterpret_cast<float*>(smem_raw + SMEM_EBUF);  // [4][64]

    const int bx = blockIdx.x, by = blockIdx.y;
    const int tid = threadIdx.x;
    const int w = tid >> 5, lane = tid & 31;
    const int wr = w >> 1, wc = w & 1;      // wr: 4 row groups of 32; wc: 2 col halves of 32

    // ---- load tiles into padded smem ----
    {
        const uint4* gA = g_imgn8 + (size_t)by * BM * (D / 16);
        const uint4* gB = g_textn8 + (size_t)bx * BN * (D / 16);
#pragma unroll
        for (int i = 0; i < 4; i++) {
            int idx = tid + i * GEMM_THREADS;          // 0..1023
            int r = idx >> 3, c = idx & 7;
            *reinterpret_cast<uint4*>(As + r * LDS8 + c * 16) = gA[idx];
        }
#pragma unroll
        for (int i = 0; i < 2; i++) {
            int idx = tid + i * GEMM_THREADS;          // 0..511
            int r = idx >> 3, c = idx & 7;
            *reinterpret_cast<uint4*>(Bs + r * LDS8 + c * 16) = gB[idx];
        }
    }
    __syncthreads();

    // ---- ldmatrix base addresses ----
    uint32_t sA = (uint32_t)__cvta_generic_to_shared(As);
    uint32_t sB = (uint32_t)__cvta_generic_to_shared(Bs);
    uint32_t aAddr[2], bAddr[2];
#pragma unroll
    for (int mt = 0; mt < 2; mt++)
        aAddr[mt] = sA + (wr * 32 + mt * 16 + (lane & 15)) * LDS8 + ((lane & 16) ? 16 : 0);
#pragma unroll
    for (int p = 0; p < 2; p++)
        bAddr[p] = sB + (wc * 32 + p * 16 + (lane & 7) + ((lane & 16) ? 8 : 0)) * LDS8 + ((lane & 8) ? 16 : 0);

    float acc[2][4][4];
#pragma unroll
    for (int mt = 0; mt < 2; mt++)
#pragma unroll
        for (int nt = 0; nt < 4; nt++)
#pragma unroll
            for (int j = 0; j < 4; j++) acc[mt][nt][j] = 0.0f;

    // ---- mainloop: 4 k-steps of 32 ----
#pragma unroll
    for (int ks = 0; ks < 4; ks++) {
        uint32_t a[2][4];
#pragma unroll
        for (int mt = 0; mt < 2; mt++)
            asm volatile("ldmatrix.sync.aligned.m8n8.x4.shared.b16 {%0,%1,%2,%3}, [%4];\n"
                         : "=r"(a[mt][0]), "=r"(a[mt][1]), "=r"(a[mt][2]), "=r"(a[mt][3])
                         : "r"(aAddr[mt] + ks * 32));
        uint32_t b[2][4];
#pragma unroll
        for (int p = 0; p < 2; p++)
            asm volatile("ldmatrix.sync.aligned.m8n8.x4.shared.b16 {%0,%1,%2,%3}, [%4];\n"
                         : "=r"(b[p][0]), "=r"(b[p][1]), "=r"(b[p][2]), "=r"(b[p][3])
                         : "r"(bAddr[p] + ks * 32));
#pragma unroll
        for (int mt = 0; mt < 2; mt++)
#pragma unroll
            for (int nt = 0; nt < 4; nt++)
                mma_fp8(acc[mt][nt], a[mt], b[nt >> 1][(nt & 1) * 2], b[nt >> 1][(nt & 1) * 2 + 1]);
    }

    // ---- epilogue ----
    float csum = 0.0f;   // this lane's col partial (sum of e over the warp's 2 bi groups)
#pragma unroll
    for (int mt = 0; mt < 2; mt++) {
        const int bi = by * 8 + wr * 2 + mt;
        float M0s[4], M1s[4];
#pragma unroll
        for (int nt = 0; nt < 4; nt++) {
            float m0 = fmaxf(acc[mt][nt][0], acc[mt][nt][2]);
            float m1 = fmaxf(acc[mt][nt][1], acc[mt][nt][3]);
#pragma unroll
            for (int s = 4; s < 32; s <<= 1) {
                m0 = fmaxf(m0, __shfl_xor_sync(0xffffffffu, m0, s));
                m1 = fmaxf(m1, __shfl_xor_sync(0xffffffffu, m1, s));
            }
            M0s[nt] = m0; M1s[nt] = m1;   // value depends only on lane&3 after tree
        }
        // redistribute: lane L owns warp-col L: nt=L>>3, cls=(L>>1)&3, parity=L&1
        float mv = 0.0f;
#pragma unroll
        for (int nt = 0; nt < 4; nt++) {
            float t0 = __shfl_sync(0xffffffffu, M0s[nt], (lane >> 1) & 3);
            float t1 = __shfl_sync(0xffffffffu, M1s[nt], (lane >> 1) & 3);
            if ((lane >> 3) == nt) mv = (lane & 1) ? t1 : t0;
        }
        float e = __expf(mv);
        csum += e;
        // per-bi i2t partial over this warp's 32 cols
        float ls = e;
#pragma unroll
        for (int s = 1; s < 32; s <<= 1) ls += __shfl_xor_sync(0xffffffffu, ls, s);
        if (lane == 0) g_part_i2t[bi * 128 + bx * 2 + wc] = ls;   // unique writer
        // diagonal capture
        int gc = bx * 64 + wc * 32 + lane;
        if ((gc >> 3) == bi) g_mdiag[bi * 8 + (gc & 7)] = mv;
    }
    // per-column partial over this warp's 32 rows (2 bi groups) -> ebuf
    ebuf[wr * 64 + wc * 32 + lane] = csum;
    __syncthreads();
    if (tid < 64) {
        float s = ebuf[tid] + ebuf[64 + tid] + ebuf[128 + tid] + ebuf[192 + tid];
        g_part_t2i[(bx * 64 + tid) * NBY + by] = s;               // unique writer
    }
}

// ============================================================
// Kernel 3: per-bi loss contribution. warp per bi, 8 warps/block.
// ============================================================
__global__ void reduce_bi_kernel() {
    __shared__ float red[8];
    int w = threadIdx.x >> 5, lane = threadIdx.x & 31;
    int bi = blockIdx.x * 8 + w;
    int t = lane >> 2, q = lane & 3;
    const float4* p = reinterpret_cast<const float4*>(&g_part_t2i[(bi * 8 + t) * NBY + q * 16]);
    float4 x0 = p[0], x1 = p[1], x2 = p[2], x3 = p[3];
    float s = ((x0.x + x0.y) + (x0.z + x0.w)) + ((x1.x + x1.y) + (x1.z + x1.w))
            + ((x2.x + x2.y) + (x2.z + x2.w)) + ((x3.x + x3.y) + (x3.z + x3.w));
    s += __shfl_xor_sync(0xffffffffu, s, 1);
    s += __shfl_xor_sync(0xffffffffu, s, 2);
    float v = (q == 0) ? __logf(s) : 0.0f;
    // den_i2t over 128 partials (float4 per lane)
    float4 di = reinterpret_cast<const float4*>(&g_part_i2t[bi * 128])[lane];
    float den = (di.x + di.y) + (di.z + di.w);
    float md = (lane < 8) ? g_mdiag[bi * 8 + lane] : 0.0f;
#pragma unroll
    for (int sh = 1; sh < 32; sh <<= 1) {
        v   += __shfl_xor_sync(0xffffffffu, v, sh);
        den += __shfl_xor_sync(0xffffffffu, den, sh);
        md  += __shfl_xor_sync(0xffffffffu, md, sh);
    }
    if (lane == 0) red[w] = __logf(den) + v - 1.125f * md;
    __syncthreads();
    if (threadIdx.x == 0) {
        float c = 0.0f;
#pragma unroll
        for (int i = 0; i < 8; i++) c += red[i];
        g_blockpart[blockIdx.x] = c;
    }
}

// ============================================================
// Kernel 4: tiny final sum over 64 block partials
// ============================================================
__global__ void final_kernel(float* __restrict__ out) {
    int lane = threadIdx.x;
    float s = g_blockpart[lane] + g_blockpart[lane + 32];
#pragma unroll
    for (int sh = 16; sh > 0; sh >>= 1) s += __shfl_xor_sync(0xffffffffu, s, sh);
    if (lane == 0) out[0] = s;
}

// ============================================================
extern "C" void kernel_launch(void* const* d_in, const int* in_sizes, int n_in,
                              void* d_out, int out_size) {
    const float* img  = (const float*)d_in[0];   // (512,16,128) f32
    const float* text = (const float*)d_in[1];   // (512,8,128) f32
    float* out = (float*)d_out;

    cudaFuncSetAttribute(gemm_kernel, cudaFuncAttributeMaxDynamicSharedMemorySize, SMEM_TOTAL);

    normalize_kernel<<<(MROWS + NROWS) / 4 * 32 / 256, 256>>>(img, text);
    gemm_kernel<<<dim3(NBX, NBY), GEMM_THREADS, SMEM_TOTAL>>>();
    reduce_bi_kernel<<<B_SZ / 8, 256>>>();
    final_kernel<<<1, 32>>>(out);
}

// round 12
// speedup vs baseline: 1.1052x; 1.1052x over previous
#include <cuda_runtime.h>
#include <cuda_bf16.h>
#include <cstdint>

// Problem constants
#define B_SZ  512
#define ZI    16
#define T_SZ  8
#define D     128
#define MROWS (B_SZ * ZI)   // 8192 img rows
#define NROWS (B_SZ * T_SZ) // 4096 text rows

// Transposed GEMM: A = text (M=4096), B = img (N=8192)
// block 128x128, warp tile 32x64, fp8 k-step 32
#define BM    128
#define BN    128
#define LDS8  144           // padded fp8 row stride in bytes (conflict-free)
#define GEMM_THREADS 256
#define NIB   (MROWS / BN)  // 64 img blocks (grid.x)
#define NTB   (NROWS / BM)  // 32 text blocks (grid.y)

// dynamic smem layout (bytes)
#define SMEM_A     0
#define SMEM_B     (BM * LDS8)              // 18432
#define SMEM_EBUF  (SMEM_B + BN * LDS8)     // 36864
#define SMEM_TOTAL (SMEM_EBUF + 2 * 128 * 4)

// -------- device scratch (no allocations; zero-initialized) --------
__device__ uint4 g_imgn8[MROWS * D / 16];    // normalized img, e4m3, 1 MB
__device__ uint4 g_textn8[NROWS * D / 16];   // normalized text, e4m3, 0.5 MB
__device__ float g_part_i2t[B_SZ * 128];     // [bi][by*4+wr] partial exp-sums
__device__ float g_part_t2i[NROWS * NIB];    // [text_row][bx] partial exp-sums
__device__ float g_mdiag[B_SZ * T_SZ];       // M[bi,bi,t]
__device__ float g_blockpart[B_SZ / 8];      // per-block loss partials (64)

// ============================================================
// Kernel 1: L2 normalize rows of 128 f32 -> e4m3; 4 rows per warp
// ============================================================
__global__ void normalize_kernel(const float* __restrict__ img,
                                 const float* __restrict__ text) {
    int gw   = (blockIdx.x * blockDim.x + threadIdx.x) >> 5;  // warp id
    int lane = threadIdx.x & 31;
    int r0 = gw * 4;                       // rows r0..r0+3 (never straddle tensors)
    const float* src;
    uint32_t* dst;
    int lrow;
    if (r0 < MROWS) { src = img;  lrow = r0;         dst = reinterpret_cast<uint32_t*>(g_imgn8); }
    else            { src = text; lrow = r0 - MROWS; dst = reinterpret_cast<uint32_t*>(g_textn8); }
    float4 v[4];
#pragma unroll
    for (int r = 0; r < 4; r++)
        v[r] = reinterpret_cast<const float4*>(src)[(lrow + r) * 32 + lane];
    float ss[4];
#pragma unroll
    for (int r = 0; r < 4; r++)
        ss[r] = v[r].x * v[r].x + v[r].y * v[r].y + v[r].z * v[r].z + v[r].w * v[r].w;
#pragma unroll
    for (int s = 16; s > 0; s >>= 1) {
#pragma unroll
        for (int r = 0; r < 4; r++)
            ss[r] += __shfl_xor_sync(0xffffffffu, ss[r], s);
    }
#pragma unroll
    for (int r = 0; r < 4; r++) {
        float inv = rsqrtf(fmaxf(ss[r], 1e-24f));
        uint32_t pack;
        asm("{ .reg .b16 lo, hi;\n\t"
            "cvt.rn.satfinite.e4m3x2.f32 lo, %2, %1;\n\t"
            "cvt.rn.satfinite.e4m3x2.f32 hi, %4, %3;\n\t"
            "mov.b32 %0, {lo, hi}; }"
            : "=r"(pack)
            : "f"(v[r].x * inv), "f"(v[r].y * inv), "f"(v[r].z * inv), "f"(v[r].w * inv));
        dst[(lrow + r) * 32 + lane] = pack;
    }
}

// dummy no-op kernels to align ncu's capture index onto the GEMM
__global__ void dummy_kernel() {}

// ============================================================
// Kernel 2: fp8 GEMM (transposed: C[text][img]) + in-fragment max_i
// ============================================================
extern __shared__ char smem_raw[];

__device__ __forceinline__ void mma_fp8(float* c, const uint32_t* a, uint32_t b0, uint32_t b1) {
    asm volatile(
        "mma.sync.aligned.m16n8k32.row.col.f32.e4m3.e4m3.f32 "
        "{%0,%1,%2,%3}, {%4,%5,%6,%7}, {%8,%9}, {%0,%1,%2,%3};\n"
        : "+f"(c[0]), "+f"(c[1]), "+f"(c[2]), "+f"(c[3])
        : "r"(a[0]), "r"(a[1]), "r"(a[2]), "r"(a[3]), "r"(b0), "r"(b1));
}

__global__ void __launch_bounds__(GEMM_THREADS, 2)
gemm_kernel() {
    char* As = smem_raw + SMEM_A;    // [128][144] fp8  (text rows)
    char* Bs = smem_raw + SMEM_B;    // [128][144] fp8  (img rows = C cols)
    float* ebuf = reinterpret_cast<float*>(smem_raw + SMEM_EBUF);  // [2][128]

    const int bx = blockIdx.x, by = blockIdx.y;   // bx: img block (N), by: text block (M)
    const int tid = threadIdx.x;
    const int w = tid >> 5, lane = tid & 31;
    const int wr = w >> 1, wc = w & 1;            // wr: 4 row groups of 32; wc: 2 col halves of 64
    const int grp = lane >> 2, cls = lane & 3;

    // ---- load tiles (A=text, B=img; each 128x128 fp8 = 16KB) ----
    {
        const uint4* gA = g_textn8 + (size_t)by * BM * (D / 16);
        const uint4* gB = g_imgn8 + (size_t)bx * BN * (D / 16);
#pragma unroll
        for (int i = 0; i < 4; i++) {
            int idx = tid + i * GEMM_THREADS;          // 0..1023
            int r = idx >> 3, c = idx & 7;
            *reinterpret_cast<uint4*>(As + r * LDS8 + c * 16) = gA[idx];
            *reinterpret_cast<uint4*>(Bs + r * LDS8 + c * 16) = gB[idx];
        }
    }
    __syncthreads();

    // ---- ldmatrix base addresses (fp8: k-half = 16 bytes) ----
    uint32_t sA = (uint32_t)__cvta_generic_to_shared(As);
    uint32_t sB = (uint32_t)__cvta_generic_to_shared(Bs);
    uint32_t aAddr[2], bAddr[4];
#pragma unroll
    for (int mt = 0; mt < 2; mt++)
        aAddr[mt] = sA + (wr * 32 + mt * 16 + (lane & 15)) * LDS8 + ((lane & 16) ? 16 : 0);
#pragma unroll
    for (int p = 0; p < 4; p++)
        bAddr[p] = sB + (wc * 64 + p * 16 + (lane & 7) + ((lane & 16) ? 8 : 0)) * LDS8 + ((lane & 8) ? 16 : 0);

    float acc[2][8][4];
#pragma unroll
    for (int mt = 0; mt < 2; mt++)
#pragma unroll
        for (int nt = 0; nt < 8; nt++)
#pragma unroll
            for (int j = 0; j < 4; j++) acc[mt][nt][j] = 0.0f;

    // ---- mainloop: 4 k-steps of 32 ----
#pragma unroll
    for (int ks = 0; ks < 4; ks++) {
        uint32_t a[2][4];
#pragma unroll
        for (int mt = 0; mt < 2; mt++)
            asm volatile("ldmatrix.sync.aligned.m8n8.x4.shared.b16 {%0,%1,%2,%3}, [%4];\n"
                         : "=r"(a[mt][0]), "=r"(a[mt][1]), "=r"(a[mt][2]), "=r"(a[mt][3])
                         : "r"(aAddr[mt] + ks * 32));
        uint32_t b[4][4];
#pragma unroll
        for (int p = 0; p < 4; p++)
            asm volatile("ldmatrix.sync.aligned.m8n8.x4.shared.b16 {%0,%1,%2,%3}, [%4];\n"
                         : "=r"(b[p][0]), "=r"(b[p][1]), "=r"(b[p][2]), "=r"(b[p][3])
                         : "r"(bAddr[p] + ks * 32));
#pragma unroll
        for (int mt = 0; mt < 2; mt++)
#pragma unroll
            for (int nt = 0; nt < 8; nt++)
                mma_fp8(acc[mt][nt], a[mt], b[nt >> 1][(nt & 1) * 2], b[nt >> 1][(nt & 1) * 2 + 1]);
    }

    // ---- epilogue: max over i = in-fragment column max over 16 cols ----
    // bigroup G covers cols 16G..16G+15 (nt = 2G, 2G+1); lane cls==G owns it
    float m_lo[2], m_hi[2];         // selected m for G==cls, rows grp / grp+8 (per mt)
#pragma unroll
    for (int G = 0; G < 4; G++) {
#pragma unroll
        for (int mt = 0; mt < 2; mt++) {
            float a0 = fmaxf(fmaxf(acc[mt][2 * G][0], acc[mt][2 * G][1]),
                             fmaxf(acc[mt][2 * G + 1][0], acc[mt][2 * G + 1][1]));
            float a1 = fmaxf(fmaxf(acc[mt][2 * G][2], acc[mt][2 * G][3]),
                             fmaxf(acc[mt][2 * G + 1][2], acc[mt][2 * G + 1][3]));
            a0 = fmaxf(a0, __shfl_xor_sync(0xffffffffu, a0, 1));
            a0 = fmaxf(a0, __shfl_xor_sync(0xffffffffu, a0, 2));
            a1 = fmaxf(a1, __shfl_xor_sync(0xffffffffu, a1, 1));
            a1 = fmaxf(a1, __shfl_xor_sync(0xffffffffu, a1, 2));
            if (cls == G) { m_lo[mt] = a0; m_hi[mt] = a1; }
        }
    }
    float e_lo[2], e_hi[2];
#pragma unroll
    for (int mt = 0; mt < 2; mt++) { e_lo[mt] = __expf(m_lo[mt]); e_hi[mt] = __expf(m_hi[mt]); }

    // den_t2i row partials: sum over the warp's 4 bigroups (= over cls lanes)
    float rs_lo[2], rs_hi[2];
#pragma unroll
    for (int mt = 0; mt < 2; mt++) {
        float x = e_lo[mt];
        x += __shfl_xor_sync(0xffffffffu, x, 1);
        x += __shfl_xor_sync(0xffffffffu, x, 2);
        rs_lo[mt] = x;
        float y = e_hi[mt];
        y += __shfl_xor_sync(0xffffffffu, y, 1);
        y += __shfl_xor_sync(0xffffffffu, y, 2);
        rs_hi[mt] = y;
    }
    if (cls == 0) {
#pragma unroll
        for (int mt = 0; mt < 2; mt++) {
            int rl = wr * 32 + mt * 16 + grp;
            ebuf[wc * 128 + rl]     = rs_lo[mt];
            ebuf[wc * 128 + rl + 8] = rs_hi[mt];
        }
    }

    // den_i2t bigroup partials: sum over the warp's 32 text rows
    const int bi_g = bx * 8 + wc * 4 + cls;
    float ts = (e_lo[0] + e_hi[0]) + (e_lo[1] + e_hi[1]);
    ts += __shfl_xor_sync(0xffffffffu, ts, 4);
    ts += __shfl_xor_sync(0xffffffffu, ts, 8);
    ts += __shfl_xor_sync(0xffffffffu, ts, 16);
    if (grp == 0) g_part_i2t[bi_g * 128 + by * 4 + wr] = ts;   // unique writer

    // diagonal capture: text row's bt must equal bi_g
#pragma unroll
    for (int mt = 0; mt < 2; mt++) {
        int row = by * 128 + wr * 32 + mt * 16 + grp;
        if ((row >> 3) == bi_g)       g_mdiag[bi_g * 8 + (row & 7)]       = m_lo[mt];
        if (((row + 8) >> 3) == bi_g) g_mdiag[bi_g * 8 + ((row + 8) & 7)] = m_hi[mt];
    }

    __syncthreads();
    if (tid < 128) {   // combine the two col-halves; one writer per text row
        float v = ebuf[tid] + ebuf[128 + tid];
        g_part_t2i[(by * 128 + tid) * NIB + bx] = v;           // unique writer
    }
}

// ============================================================
// Kernel 3: per-bi loss contribution. warp per bi, 8 warps/block.
// ============================================================
__global__ void reduce_bi_kernel() {
    __shared__ float red[8];
    int w = threadIdx.x >> 5, lane = threadIdx.x & 31;
    int bi = blockIdx.x * 8 + w;
    int t = lane >> 2, q = lane & 3;
    const float4* p = reinterpret_cast<const float4*>(&g_part_t2i[(bi * 8 + t) * NIB + q * 16]);
    float4 x0 = p[0], x1 = p[1], x2 = p[2], x3 = p[3];
    float s = ((x0.x + x0.y) + (x0.z + x0.w)) + ((x1.x + x1.y) + (x1.z + x1.w))
            + ((x2.x + x2.y) + (x2.z + x2.w)) + ((x3.x + x3.y) + (x3.z + x3.w));
    s += __shfl_xor_sync(0xffffffffu, s, 1);
    s += __shfl_xor_sync(0xffffffffu, s, 2);
    float v = (q == 0) ? __logf(s) : 0.0f;
    // den_i2t over 128 partials (float4 per lane)
    float4 di = reinterpret_cast<const float4*>(&g_part_i2t[bi * 128])[lane];
    float den = (di.x + di.y) + (di.z + di.w);
    float md = (lane < 8) ? g_mdiag[bi * 8 + lane] : 0.0f;
#pragma unroll
    for (int sh = 1; sh < 32; sh <<= 1) {
        v   += __shfl_xor_sync(0xffffffffu, v, sh);
        den += __shfl_xor_sync(0xffffffffu, den, sh);
        md  += __shfl_xor_sync(0xffffffffu, md, sh);
    }
    if (lane == 0) red[w] = __logf(den) + v - 1.125f * md;
    __syncthreads();
    if (threadIdx.x == 0) {
        float c = 0.0f;
#pragma unroll
        for (int i = 0; i < 8; i++) c += red[i];
        g_blockpart[blockIdx.x] = c;
    }
}

// ============================================================
// Kernel 4: tiny final sum over 64 block partials
// ============================================================
__global__ void final_kernel(float* __restrict__ out) {
    int lane = threadIdx.x;
    float s = g_blockpart[lane] + g_blockpart[lane + 32];
#pragma unroll
    for (int sh = 16; sh > 0; sh >>= 1) s += __shfl_xor_sync(0xffffffffu, s, sh);
    if (lane == 0) out[0] = s;
}

// ============================================================
extern "C" void kernel_launch(void* const* d_in, const int* in_sizes, int n_in,
                              void* d_out, int out_size) {
    const float* img  = (const float*)d_in[0];   // (512,16,128) f32
    const float* text = (const float*)d_in[1];   // (512,8,128) f32
    float* out = (float*)d_out;

    cudaFuncSetAttribute(gemm_kernel, cudaFuncAttributeMaxDynamicSharedMemorySize, SMEM_TOTAL);

    normalize_kernel<<<(MROWS + NROWS) / 4 * 32 / 256, 256>>>(img, text);
    dummy_kernel<<<1, 32>>>();   // align ncu capture index (empirically launch #3)
    dummy_kernel<<<1, 32>>>();   // onto the GEMM below
    gemm_kernel<<<dim3(NIB, NTB), GEMM_THREADS, SMEM_TOTAL>>>();
    reduce_bi_kernel<<<B_SZ / 8, 256>>>();
    final_kernel<<<1, 32>>>(out);
}